// round 3
// baseline (speedup 1.0000x reference)
#include <cuda_runtime.h>

#define BATCH 65536
#define D 128
#define OUTW 896          // D*6 + D
#define ROWS 32           // batch rows per block
#define THREADS 256
#define XS_STRIDE 129     // padded row stride for x_s (conflict-free column reads)
#define STG_STRIDE 14     // padded per-i stage stride: pads absorb j-3..j overflow
#define STG_ROW (D * STG_STRIDE)   // 1792 floats per staged row

__device__ float g_S[D * D];   // sigmoid(W), row-major [i][j]

// ---------------- f32x2 packed-FMA helpers (Blackwell FFMA2) ----------------
__device__ __forceinline__ unsigned long long pack2(float lo, float hi) {
    unsigned long long r;
    asm("mov.b64 %0, {%1, %2};" : "=l"(r) : "f"(lo), "f"(hi));
    return r;
}
__device__ __forceinline__ unsigned long long fma2(unsigned long long a,
                                                   unsigned long long b,
                                                   unsigned long long c) {
    unsigned long long d;
    asm("fma.rn.f32x2 %0, %1, %2, %3;" : "=l"(d) : "l"(a), "l"(b), "l"(c));
    return d;
}
__device__ __forceinline__ void unpack2(unsigned long long v, float& lo, float& hi) {
    asm("mov.b64 {%0, %1}, %2;" : "=f"(lo), "=f"(hi) : "l"(v));
}

// ---------------- kernel 1: S = sigmoid(W) ----------------
__global__ void sigmoid_kernel(const float* __restrict__ W) {
    int idx = blockIdx.x * blockDim.x + threadIdx.x;
    if (idx < D * D) {
        float w = W[idx];
        g_S[idx] = 1.0f / (1.0f + expf(-w));
    }
}

// ---------------- kernel 2: fused interaction + basis ----------------
__global__ __launch_bounds__(THREADS) void kan_kernel(const float* __restrict__ x,
                                                      float* __restrict__ out) {
    __shared__ float x_s[ROWS * XS_STRIDE];   // raw x tile, padded
    __shared__ float x2p_s[D * ROWS];         // x^2 transposed; later reused as stage

    const int tid = threadIdx.x;
    const int r0 = blockIdx.x * ROWS;

    // ---- load x tile: 32 rows x 128 f32 = 1024 float4 (coalesced) ----
    const float4* xg = (const float4*)(x + (size_t)r0 * D);
#pragma unroll
    for (int k = 0; k < 4; k++) {
        int q = tid + k * 256;              // 0..1023
        int row = q >> 5;
        int c4 = q & 31;
        float4 v = xg[row * 32 + c4];
        float* dst = &x_s[row * XS_STRIDE + c4 * 4];
        dst[0] = v.x; dst[1] = v.y; dst[2] = v.z; dst[3] = v.w;
    }
    __syncthreads();

    // ---- transpose + square into x2p_s (conflict-free) ----
#pragma unroll
    for (int k = 0; k < 16; k++) {
        int idx = tid + k * 256;            // 0..4095
        int row = idx & 31;
        int i = idx >> 5;
        float v = x_s[row * XS_STRIDE + i];
        x2p_s[i * ROWS + row] = v * v;
    }
    __syncthreads();

    // ---- phase A: interaction GEMM  out[b, 768+c] = sum_i x2[b,i]*S[i,c] ----
    {
        const int c = tid & 127;       // output column
        const int g = tid >> 7;        // row-half
        const int rbase = g * 16;

        unsigned long long a0 = 0ull, a1 = 0ull, a2 = 0ull, a3 = 0ull,
                           a4 = 0ull, a5 = 0ull, a6 = 0ull, a7 = 0ull;

#pragma unroll 4
        for (int i = 0; i < D; i++) {
            float s = __ldg(&g_S[i * D + c]);   // coalesced, L1-resident
            unsigned long long s2 = pack2(s, s);
            const ulonglong2* xp = (const ulonglong2*)&x2p_s[i * ROWS + rbase];
            ulonglong2 p0 = xp[0];
            ulonglong2 p1 = xp[1];
            ulonglong2 p2 = xp[2];
            ulonglong2 p3 = xp[3];
            a0 = fma2(p0.x, s2, a0);
            a1 = fma2(p0.y, s2, a1);
            a2 = fma2(p1.x, s2, a2);
            a3 = fma2(p1.y, s2, a3);
            a4 = fma2(p2.x, s2, a4);
            a5 = fma2(p2.y, s2, a5);
            a6 = fma2(p3.x, s2, a6);
            a7 = fma2(p3.y, s2, a7);
        }

        float lo, hi;
        float* ob = out + 768 + c;
        size_t rs = (size_t)(r0 + rbase) * OUTW;
        unpack2(a0, lo, hi); ob[rs] = lo;            ob[rs + OUTW] = hi;
        unpack2(a1, lo, hi); ob[rs + 2*OUTW] = lo;   ob[rs + 3*OUTW] = hi;
        unpack2(a2, lo, hi); ob[rs + 4*OUTW] = lo;   ob[rs + 5*OUTW] = hi;
        unpack2(a3, lo, hi); ob[rs + 6*OUTW] = lo;   ob[rs + 7*OUTW] = hi;
        unpack2(a4, lo, hi); ob[rs + 8*OUTW] = lo;   ob[rs + 9*OUTW] = hi;
        unpack2(a5, lo, hi); ob[rs + 10*OUTW] = lo;  ob[rs + 11*OUTW] = hi;
        unpack2(a6, lo, hi); ob[rs + 12*OUTW] = lo;  ob[rs + 13*OUTW] = hi;
        unpack2(a7, lo, hi); ob[rs + 14*OUTW] = lo;  ob[rs + 15*OUTW] = hi;
    }

    // ---- phase B: B-spline basis via padded smem scatter + dense copy-out ----
    // 16 chunks of 2 rows. Stage layout: stage[lrow*1792 + i*14 + 4 + k],
    // k in [-3..8] always in-bounds (front pad 4, rear pad 2).
    const float s6 = 1.0f / 6.0f;
    const float xmax = 1.0f - 1e-6f;
    float* stage = x2p_s;                       // reuse (needs 3584 <= 4096)
    const int lrow_s = tid >> 7;                // 0/1: scatter row
    const int i_s = tid & 127;
    float* sp = &stage[lrow_s * STG_ROW + i_s * STG_STRIDE + 4];

#pragma unroll 1
    for (int ch = 0; ch < 16; ch++) {
        __syncthreads();                        // stage free (GEMM / prev copy-out done)
        // -- scatter: one element per thread, single eval, no select chain --
        {
            float xv = x_s[(ch * 2 + lrow_s) * XS_STRIDE + i_s];
            float xc = fminf(fmaxf(xv, -1.0f), xmax);
            float p = (xc + 1.0f) * 4.5f;       // p in [0, 9)
            int j = (int)p;                     // 0..8, no clamp needed
            float u = p - (float)j;
            float u2 = u * u;
            float u3 = u2 * u;
            float om = 1.0f - u;
            float N0 = om * om * om * s6;
            float N1 = (3.0f * u3 - 6.0f * u2 + 4.0f) * s6;
            float N2 = (-3.0f * u3 + 3.0f * u2 + 3.0f * u + 1.0f) * s6;
            float N3 = u3 * s6;

            float2 z2 = make_float2(0.0f, 0.0f);
            *(float2*)(sp + 0) = z2;            // zero real slots k=0..5
            *(float2*)(sp + 2) = z2;
            *(float2*)(sp + 4) = z2;
            sp[j - 3] = N0;                     // scatter window (pads absorb OOB)
            sp[j - 2] = N1;
            sp[j - 1] = N2;
            sp[j]     = N3;
        }
        __syncthreads();
        // -- dense copy-out: 768 float2 per chunk, 3 per thread --
#pragma unroll
        for (int e = 0; e < 3; e++) {
            int h = tid + e * 256;              // float2 index in chunk, 0..767
            int lr = h / 384;                   // 384 float2 per row
            int hf = h - lr * 384;
            int i = hf / 3;                     // float2 never crosses an i-group
            int k = 2 * (hf - i * 3);
            float2 v = *(const float2*)&stage[lr * STG_ROW + i * STG_STRIDE + 4 + k];
            *(float2*)&out[(size_t)(r0 + ch * 2 + lr) * OUTW + hf * 2] = v;
        }
    }
}

extern "C" void kernel_launch(void* const* d_in, const int* in_sizes, int n_in,
                              void* d_out, int out_size) {
    const float* x;
    const float* W;
    if (n_in >= 2 && in_sizes[0] == D * D && in_sizes[1] != D * D) {
        W = (const float*)d_in[0];
        x = (const float*)d_in[1];
    } else {
        x = (const float*)d_in[0];
        W = (const float*)d_in[1];
    }
    float* out = (float*)d_out;

    sigmoid_kernel<<<(D * D + 255) / 256, 256>>>(W);
    kan_kernel<<<BATCH / ROWS, THREADS>>>(x, out);
}

// round 6
// speedup vs baseline: 1.1879x; 1.1879x over previous
#include <cuda_runtime.h>

#define BATCH 65536
#define D 128
#define OUTW 896          // D*6 + D
#define ROWS 32           // batch rows per block
#define THREADS 256
#define XS_STRIDE 129     // padded row stride for x_s (conflict-free column reads)
#define SLOTS_PER_ROW 384 // 768 basis floats per row = 384 float2 slots
#define TOTAL_SLOTS (ROWS * SLOTS_PER_ROW)   // 12288 per block

__device__ float g_S[D * D];   // sigmoid(W), row-major [i][j]

// ---------------- f32x2 packed-FMA helpers (Blackwell FFMA2) ----------------
__device__ __forceinline__ unsigned long long pack2(float lo, float hi) {
    unsigned long long r;
    asm("mov.b64 %0, {%1, %2};" : "=l"(r) : "f"(lo), "f"(hi));
    return r;
}
__device__ __forceinline__ unsigned long long fma2(unsigned long long a,
                                                   unsigned long long b,
                                                   unsigned long long c) {
    unsigned long long d;
    asm("fma.rn.f32x2 %0, %1, %2, %3;" : "=l"(d) : "l"(a), "l"(b), "l"(c));
    return d;
}
__device__ __forceinline__ void unpack2(unsigned long long v, float& lo, float& hi) {
    asm("mov.b64 {%0, %1}, %2;" : "=f"(lo), "=f"(hi) : "l"(v));
}

// cardinal cubic B-spline: support (0,4), symmetric about y=2.
// y in [0,1]:   y^3/6
// y in [1,2]:   t^2*(t/2 - 1) + 2/3 with t = 2 - y   (mirrored for y>2)
__device__ __forceinline__ float bspl(float y) {
    float z = fminf(y, 4.0f - y);
    z = fmaxf(z, 0.0f);
    float lo = z * z * z * (1.0f / 6.0f);
    float t = 2.0f - z;
    float hi = fmaf(t * t, fmaf(t, 0.5f, -1.0f), 2.0f / 3.0f);
    return (z < 1.0f) ? lo : hi;
}

// ---------------- kernel 1: S = sigmoid(W) ----------------
__global__ void sigmoid_kernel(const float* __restrict__ W) {
    int idx = blockIdx.x * blockDim.x + threadIdx.x;
    if (idx < D * D) {
        float w = W[idx];
        g_S[idx] = 1.0f / (1.0f + expf(-w));
    }
}

// ---------------- kernel 2: fused basis + interaction ----------------
__global__ __launch_bounds__(THREADS) void kan_kernel(const float* __restrict__ x,
                                                      float* __restrict__ out) {
    __shared__ float x_s[ROWS * XS_STRIDE];   // raw x tile, padded
    __shared__ float x2p_s[D * ROWS];         // x^2, transposed: [i][row]

    const int tid = threadIdx.x;
    const int r0 = blockIdx.x * ROWS;

    // ---- load x tile: 32 rows x 128 f32 = 1024 float4 (coalesced) ----
    const float4* xg = (const float4*)(x + (size_t)r0 * D);
#pragma unroll
    for (int k = 0; k < 4; k++) {
        int q = tid + k * 256;              // 0..1023
        int row = q >> 5;
        int c4 = q & 31;
        float4 v = xg[row * 32 + c4];
        float* dst = &x_s[row * XS_STRIDE + c4 * 4];
        dst[0] = v.x; dst[1] = v.y; dst[2] = v.z; dst[3] = v.w;
    }
    __syncthreads();

    // ---- transpose + square into x2p_s (conflict-free) ----
#pragma unroll
    for (int k = 0; k < 16; k++) {
        int idx = tid + k * 256;            // 0..4095
        int row = idx & 31;
        int i = idx >> 5;
        float v = x_s[row * XS_STRIDE + i];
        x2p_s[i * ROWS + row] = v * v;
    }
    __syncthreads();

    // ---- phase A: B-spline basis, dense float2 stores, cardinal closed form --
    // Slot q: row = q/384, p = q%384, i = p/3, pair = p%3.
    // out[b, 6i+k] = B(px - k) with px = (clip(x)+1)*4.5 in [0,9).
#pragma unroll 6
    for (int k = 0; k < TOTAL_SLOTS / THREADS; k++) {   // 48 iterations
        int q = tid + k * THREADS;
        int row = q / SLOTS_PER_ROW;
        int p = q - row * SLOTS_PER_ROW;
        int i = p / 3;
        int pr = p - i * 3;                 // 0,1,2 -> output floats 2pr, 2pr+1

        float xv = x_s[row * XS_STRIDE + i];
        float px = fminf(fmaxf(fmaf(xv, 4.5f, 4.5f), 0.0f), 8.9999955f);
        float y0 = px - (float)(2 * pr);
        float v0 = bspl(y0);
        float v1 = bspl(y0 - 1.0f);

        float2* op = (float2*)(out + (size_t)(r0 + row) * OUTW) + p;
        *op = make_float2(v0, v1);
    }

    // ---- phase B: interaction GEMM  out[b, 768+c] = sum_i x2[b,i]*S[i,c] ----
    const int c = tid & 127;       // output column
    const int g = tid >> 7;        // row-half: 0 -> rows 0..15, 1 -> rows 16..31
    const int rbase = g * 16;

    unsigned long long a0 = 0ull, a1 = 0ull, a2 = 0ull, a3 = 0ull,
                       a4 = 0ull, a5 = 0ull, a6 = 0ull, a7 = 0ull;

#pragma unroll 4
    for (int i = 0; i < D; i++) {
        float s = __ldg(&g_S[i * D + c]);   // coalesced, L1-resident
        unsigned long long s2 = pack2(s, s);
        const ulonglong2* xp = (const ulonglong2*)&x2p_s[i * ROWS + rbase];
        ulonglong2 p0 = xp[0];              // rows rbase+0..3  (broadcast LDS.128)
        ulonglong2 p1 = xp[1];              // rows rbase+4..7
        ulonglong2 p2 = xp[2];              // rows rbase+8..11
        ulonglong2 p3 = xp[3];              // rows rbase+12..15
        a0 = fma2(p0.x, s2, a0);
        a1 = fma2(p0.y, s2, a1);
        a2 = fma2(p1.x, s2, a2);
        a3 = fma2(p1.y, s2, a3);
        a4 = fma2(p2.x, s2, a4);
        a5 = fma2(p2.y, s2, a5);
        a6 = fma2(p3.x, s2, a6);
        a7 = fma2(p3.y, s2, a7);
    }

    float lo, hi;
    float* ob = out + 768 + c;
    size_t rs = (size_t)(r0 + rbase) * OUTW;
    unpack2(a0, lo, hi); ob[rs] = lo;            ob[rs + OUTW] = hi;
    unpack2(a1, lo, hi); ob[rs + 2*OUTW] = lo;   ob[rs + 3*OUTW] = hi;
    unpack2(a2, lo, hi); ob[rs + 4*OUTW] = lo;   ob[rs + 5*OUTW] = hi;
    unpack2(a3, lo, hi); ob[rs + 6*OUTW] = lo;   ob[rs + 7*OUTW] = hi;
    unpack2(a4, lo, hi); ob[rs + 8*OUTW] = lo;   ob[rs + 9*OUTW] = hi;
    unpack2(a5, lo, hi); ob[rs + 10*OUTW] = lo;  ob[rs + 11*OUTW] = hi;
    unpack2(a6, lo, hi); ob[rs + 12*OUTW] = lo;  ob[rs + 13*OUTW] = hi;
    unpack2(a7, lo, hi); ob[rs + 14*OUTW] = lo;  ob[rs + 15*OUTW] = hi;
}

extern "C" void kernel_launch(void* const* d_in, const int* in_sizes, int n_in,
                              void* d_out, int out_size) {
    const float* x;
    const float* W;
    if (n_in >= 2 && in_sizes[0] == D * D && in_sizes[1] != D * D) {
        W = (const float*)d_in[0];
        x = (const float*)d_in[1];
    } else {
        x = (const float*)d_in[0];
        W = (const float*)d_in[1];
    }
    float* out = (float*)d_out;

    sigmoid_kernel<<<(D * D + 255) / 256, 256>>>(W);
    kan_kernel<<<BATCH / ROWS, THREADS>>>(x, out);
}

// round 7
// speedup vs baseline: 1.2360x; 1.0404x over previous
#include <cuda_runtime.h>

#define BATCH 65536
#define D 128
#define OUTW 896            // D*6 + D
#define ROWS 64             // batch rows per block
#define THREADS 256
#define NBLOCKS (BATCH / ROWS)        // 1024
#define CHUNK 32                      // K (i) chunk size
#define X2T_STRIDE 68                 // words; 64 rows + pad, /4 aligned
#define SS_STRIDE 132                 // words; 128 cols + pad, /4 aligned
#define SLOTS_PER_ROW 384             // 768 basis floats = 384 float2
#define BAS_ITERS (ROWS * SLOTS_PER_ROW / THREADS)   // 96

__device__ float g_S[D * D];   // sigmoid(W), row-major [i][c]

// ---------------- f32x2 packed-FMA helpers ----------------
__device__ __forceinline__ unsigned long long pack2(float lo, float hi) {
    unsigned long long r;
    asm("mov.b64 %0, {%1, %2};" : "=l"(r) : "f"(lo), "f"(hi));
    return r;
}
__device__ __forceinline__ unsigned long long fma2(unsigned long long a,
                                                   unsigned long long b,
                                                   unsigned long long c) {
    unsigned long long d;
    asm("fma.rn.f32x2 %0, %1, %2, %3;" : "=l"(d) : "l"(a), "l"(b), "l"(c));
    return d;
}
__device__ __forceinline__ void unpack2(unsigned long long v, float& lo, float& hi) {
    asm("mov.b64 {%0, %1}, %2;" : "=f"(lo), "=f"(hi) : "l"(v));
}

// cardinal cubic B-spline: support (0,4), symmetric about y=2
__device__ __forceinline__ float bspl(float y) {
    float z = fminf(y, 4.0f - y);
    z = fmaxf(z, 0.0f);
    float lo = z * z * z * (1.0f / 6.0f);
    float t = 2.0f - z;
    float hi = fmaf(t * t, fmaf(t, 0.5f, -1.0f), 2.0f / 3.0f);
    return (z < 1.0f) ? lo : hi;
}

// ---------------- kernel 1: S = sigmoid(W) ----------------
__global__ void sigmoid_kernel(const float* __restrict__ W) {
    int idx = blockIdx.x * blockDim.x + threadIdx.x;
    if (idx < D * D) {
        float w = W[idx];
        g_S[idx] = 1.0f / (1.0f + expf(-w));
    }
}

// ---------------- kernel 2: fused interaction + basis ----------------
__global__ __launch_bounds__(THREADS) void kan_kernel(const float* __restrict__ x,
                                                      float* __restrict__ out) {
    __shared__ float x2T_s[CHUNK * X2T_STRIDE];   // x^2 transposed: [i_local][row]
    __shared__ float s_s[CHUNK * SS_STRIDE];      // S chunk: [i_local][c]

    const int tid = threadIdx.x;
    const int r0 = blockIdx.x * ROWS;

    // GEMM thread tile: rows rg*8..rg*8+7, cols cg*4..cg*4+3
    const int cg = tid & 31;       // warp lanes span 32 col-groups
    const int rg = tid >> 5;       // constant within a warp -> x2 LDS broadcast

    // 16 accumulators: acc[rp][k] holds rows (rg*8+2rp, +1), col cg*4+k
    unsigned long long acc[4][4];
#pragma unroll
    for (int a = 0; a < 4; a++)
#pragma unroll
        for (int b = 0; b < 4; b++) acc[a][b] = 0ull;

    // ---- GEMM over 4 K-chunks of 32 ----
#pragma unroll 1
    for (int ch = 0; ch < 4; ch++) {
        __syncthreads();            // previous chunk fully consumed
        // stage x^2 transposed: lane il owns column i = ch*32+il, rows rg*8..+7
        {
            int il = tid & 31;
            const float* xp = x + (size_t)(r0 + rg * 8) * D + ch * CHUNK + il;
            float v0 = xp[0];        float v1 = xp[D];
            float v2 = xp[2 * D];    float v3 = xp[3 * D];
            float v4 = xp[4 * D];    float v5 = xp[5 * D];
            float v6 = xp[6 * D];    float v7 = xp[7 * D];
            float* dst = &x2T_s[il * X2T_STRIDE + rg * 8];
            *(float4*)dst       = make_float4(v0 * v0, v1 * v1, v2 * v2, v3 * v3);
            *(float4*)(dst + 4) = make_float4(v4 * v4, v5 * v5, v6 * v6, v7 * v7);
        }
        // stage S chunk: straight vectorized copy [32 i][128 c]
        {
#pragma unroll
            for (int j = 0; j < 4; j++) {
                int idx = tid + j * 256;        // 0..1023 float4 slots
                int il = idx >> 5;
                int c4 = (idx & 31) * 4;
                float4 sv = *(const float4*)&g_S[(ch * CHUNK + il) * D + c4];
                *(float4*)&s_s[il * SS_STRIDE + c4] = sv;
            }
        }
        __syncthreads();
        // compute: 32 K-steps
#pragma unroll
        for (int il = 0; il < CHUNK; il++) {
            const float* xr = &x2T_s[il * X2T_STRIDE + rg * 8];
            ulonglong2 xa = *(const ulonglong2*)xr;         // rows 0..3 (broadcast)
            ulonglong2 xb = *(const ulonglong2*)(xr + 4);   // rows 4..7
            float4 s4 = *(const float4*)&s_s[il * SS_STRIDE + cg * 4];
            unsigned long long s0 = pack2(s4.x, s4.x);
            unsigned long long s1 = pack2(s4.y, s4.y);
            unsigned long long s2 = pack2(s4.z, s4.z);
            unsigned long long s3 = pack2(s4.w, s4.w);
            acc[0][0] = fma2(xa.x, s0, acc[0][0]);
            acc[1][0] = fma2(xa.y, s0, acc[1][0]);
            acc[2][0] = fma2(xb.x, s0, acc[2][0]);
            acc[3][0] = fma2(xb.y, s0, acc[3][0]);
            acc[0][1] = fma2(xa.x, s1, acc[0][1]);
            acc[1][1] = fma2(xa.y, s1, acc[1][1]);
            acc[2][1] = fma2(xb.x, s1, acc[2][1]);
            acc[3][1] = fma2(xb.y, s1, acc[3][1]);
            acc[0][2] = fma2(xa.x, s2, acc[0][2]);
            acc[1][2] = fma2(xa.y, s2, acc[1][2]);
            acc[2][2] = fma2(xb.x, s2, acc[2][2]);
            acc[3][2] = fma2(xb.y, s2, acc[3][2]);
            acc[0][3] = fma2(xa.x, s3, acc[0][3]);
            acc[1][3] = fma2(xa.y, s3, acc[1][3]);
            acc[2][3] = fma2(xb.x, s3, acc[2][3]);
            acc[3][3] = fma2(xb.y, s3, acc[3][3]);
        }
    }

    // ---- GEMM epilogue: 8 rows x 4 cols -> dense STG.64 pairs ----
    {
        float* ob = out + 768 + cg * 4;
#pragma unroll
        for (int rp = 0; rp < 4; rp++) {
            float f0l, f0h, f1l, f1h, f2l, f2h, f3l, f3h;
            unpack2(acc[rp][0], f0l, f0h);
            unpack2(acc[rp][1], f1l, f1h);
            unpack2(acc[rp][2], f2l, f2h);
            unpack2(acc[rp][3], f3l, f3h);
            size_t rlo = (size_t)(r0 + rg * 8 + 2 * rp) * OUTW;
            size_t rhi = rlo + OUTW;
            *(float2*)&ob[rlo]     = make_float2(f0l, f1l);
            *(float2*)&ob[rlo + 2] = make_float2(f2l, f3l);
            *(float2*)&ob[rhi]     = make_float2(f0h, f1h);
            *(float2*)&ob[rhi + 2] = make_float2(f2h, f3h);
        }
    }

    // ---- basis: dense float2 stores, cardinal closed form ----
    // slot q: row = q/384, p = q%384, i = p/3, pr = p%3
    const float* xb = x + (size_t)r0 * D;
#pragma unroll 4
    for (int s = 0; s < BAS_ITERS; s++) {
        int q = tid + s * THREADS;          // 0..24575
        int row = q / SLOTS_PER_ROW;
        int p = q - row * SLOTS_PER_ROW;
        int i = p / 3;
        int pr = p - i * 3;

        float xv = __ldg(&xb[row * D + i]);
        float px = fminf(fmaxf(fmaf(xv, 4.5f, 4.5f), 0.0f), 8.9999955f);
        float y0 = px - (float)(2 * pr);
        float v0 = bspl(y0);
        float v1 = bspl(y0 - 1.0f);

        float2* op = (float2*)(out + (size_t)(r0 + row) * OUTW) + p;
        *op = make_float2(v0, v1);
    }
}

extern "C" void kernel_launch(void* const* d_in, const int* in_sizes, int n_in,
                              void* d_out, int out_size) {
    const float* x;
    const float* W;
    if (n_in >= 2 && in_sizes[0] == D * D && in_sizes[1] != D * D) {
        W = (const float*)d_in[0];
        x = (const float*)d_in[1];
    } else {
        x = (const float*)d_in[0];
        W = (const float*)d_in[1];
    }
    float* out = (float*)d_out;

    sigmoid_kernel<<<(D * D + 255) / 256, 256>>>(W);
    kan_kernel<<<NBLOCKS, THREADS>>>(x, out);
}

// round 12
// speedup vs baseline: 1.2902x; 1.0439x over previous
#include <cuda_runtime.h>
#include <cuda_bf16.h>
#include <cstdint>

#define BATCH 65536
#define D 128
#define OUTW 896
#define ROWS 64                       // batch rows per block (MMA M total)
#define THREADS 256
#define NBLOCKS (BATCH / ROWS)        // 1024
#define SLOTS_PER_ROW 384
#define BAS_ITERS (ROWS * SLOTS_PER_ROW / THREADS)   // 96

// smem (bytes). bf16 tiles with padded stride 136 elems (272B = 17x16B -> ldmatrix conflict-free)
#define TSTRIDE 136
#define SM_AH 0                       // x2_hi  [64][136] bf16 = 17408 B
#define SM_AL 17408                   // x2_lo
#define SM_BH 34816                   // S^T_hi [128][136] bf16 = 34816 B
#define SM_BL 69632                   // S^T_lo
#define SM_TOTAL 104448

__device__ __align__(16) uint16_t g_SB[2 * 128 * TSTRIDE];  // [hi | lo] S^T images, padded

// ---------------- helpers ----------------
__device__ __forceinline__ uint32_t smem_u32(const void* p) {
    uint32_t a;
    asm("{ .reg .u64 t; cvta.to.shared.u64 t, %1; cvt.u32.u64 %0, t; }" : "=r"(a) : "l"(p));
    return a;
}
#define LDMX4(r0, r1, r2, r3, addr)                                        \
    asm volatile("ldmatrix.sync.aligned.m8n8.x4.shared.b16 {%0,%1,%2,%3}, [%4];" \
                 : "=r"(r0), "=r"(r1), "=r"(r2), "=r"(r3) : "r"(addr))
#define MMA16816(d, a0, a1, a2, a3, b0, b1)                                \
    asm volatile("mma.sync.aligned.m16n8k16.row.col.f32.bf16.bf16.f32 "    \
                 "{%0,%1,%2,%3}, {%4,%5,%6,%7}, {%8,%9}, {%0,%1,%2,%3};"   \
                 : "+f"((d)[0]), "+f"((d)[1]), "+f"((d)[2]), "+f"((d)[3])  \
                 : "r"(a0), "r"(a1), "r"(a2), "r"(a3), "r"(b0), "r"(b1))

// cardinal cubic B-spline: support (0,4), symmetric about y=2
__device__ __forceinline__ float bspl(float y) {
    float z = fminf(y, 4.0f - y);
    z = fmaxf(z, 0.0f);
    float lo = z * z * z * (1.0f / 6.0f);
    float t = 2.0f - z;
    float hi = fmaf(t * t, fmaf(t, 0.5f, -1.0f), 2.0f / 3.0f);
    return (z < 1.0f) ? lo : hi;
}
__device__ __forceinline__ void split_bf16(float v, uint16_t& h, uint16_t& l) {
    __nv_bfloat16 hb = __float2bfloat16(v);
    __nv_bfloat16 lb = __float2bfloat16(v - __bfloat162float(hb));
    h = __bfloat16_as_ushort(hb);
    l = __bfloat16_as_ushort(lb);
}

// ---------------- kernel 1: build S^T hi/lo padded images ----------------
__global__ void prep_kernel(const float* __restrict__ W) {
    int idx = blockIdx.x * blockDim.x + threadIdx.x;   // 16384
    if (idx < D * D) {
        int c = idx & 127;
        int i = idx >> 7;
        float s = 1.0f / (1.0f + expf(-W[i * D + c]));
        uint16_t h, l;
        split_bf16(s, h, l);
        g_SB[c * TSTRIDE + i] = h;
        g_SB[128 * TSTRIDE + c * TSTRIDE + i] = l;
    }
}

// ---------------- kernel 2: fused HMMA interaction + basis ----------------
__global__ __launch_bounds__(THREADS) void kan_kernel(const float* __restrict__ x,
                                                      float* __restrict__ out) {
    extern __shared__ __align__(16) char smem[];
    const int tid = threadIdx.x;
    const int wid = tid >> 5;
    const int lid = tid & 31;
    const int r0 = blockIdx.x * ROWS;

    // ---- stage B: raw uint4 copy of both S^T images (69632 B = 4352 uint4) ----
    {
        const uint4* gs = (const uint4*)g_SB;
        uint4* ds = (uint4*)(smem + SM_BH);
#pragma unroll
        for (int j = 0; j < 17; j++) ds[tid + j * 256] = gs[tid + j * 256];
    }
    // ---- stage A: x^2 -> bf16 hi/lo, one (row, 32-col quarter) per thread ----
    {
        int r = tid >> 2;
        int q = tid & 3;
        const float4* xp = (const float4*)(x + (size_t)(r0 + r) * D + q * 32);
        uint16_t* sah = (uint16_t*)(smem + SM_AH) + r * TSTRIDE + q * 32;
        uint16_t* sal = (uint16_t*)(smem + SM_AL) + r * TSTRIDE + q * 32;
#pragma unroll
        for (int j = 0; j < 8; j++) {
            float4 f = xp[j];
            float q0 = f.x * f.x, q1 = f.y * f.y, q2 = f.z * f.z, q3 = f.w * f.w;
            uint16_t h0, l0, h1, l1, h2, l2, h3, l3;
            split_bf16(q0, h0, l0);
            split_bf16(q1, h1, l1);
            split_bf16(q2, h2, l2);
            split_bf16(q3, h3, l3);
            uint2 hw = make_uint2((uint32_t)h0 | ((uint32_t)h1 << 16),
                                  (uint32_t)h2 | ((uint32_t)h3 << 16));
            uint2 lw = make_uint2((uint32_t)l0 | ((uint32_t)l1 << 16),
                                  (uint32_t)l2 | ((uint32_t)l3 << 16));
            *(uint2*)(sah + j * 4) = hw;
            *(uint2*)(sal + j * 4) = lw;
        }
    }
    __syncthreads();

    // ---- GEMM: warp tile 16 rows x 64 cols; 3 passes (AhBh, AlBh, AhBl) ----
    {
        const uint32_t sb = smem_u32(smem);
        const int m0 = (wid & 3) * 16;
        const int c0 = (wid >> 2) * 64;
        const int t = lid >> 3;
        const int tr = lid & 7;

        // A ldmatrix lane offset: tiles {(r0,k0),(r8,k0),(r0,k8),(r8,k8)}
        const uint32_t aoff =
            (uint32_t)((m0 + (t & 1) * 8 + tr) * (TSTRIDE * 2) + (t >> 1) * 16);
        // B ldmatrix lane offsets per n-tile-pair p: tiles {(c,k0),(c,k8),(c+8,k0),(c+8,k8)}
        uint32_t boff[4];
#pragma unroll
        for (int p = 0; p < 4; p++)
            boff[p] = (uint32_t)((c0 + p * 16 + (t >> 1) * 8 + tr) * (TSTRIDE * 2) +
                                 (t & 1) * 16);

        float acc[8][4];
#pragma unroll
        for (int n = 0; n < 8; n++)
#pragma unroll
            for (int j = 0; j < 4; j++) acc[n][j] = 0.0f;

        const uint32_t abase[3] = {sb + SM_AH, sb + SM_AL, sb + SM_AH};
        const uint32_t bbase[3] = {sb + SM_BH, sb + SM_BH, sb + SM_BL};

#pragma unroll 1
        for (int pass = 0; pass < 3; pass++) {
            uint32_t ab = abase[pass] + aoff;
            uint32_t bbs = bbase[pass];
#pragma unroll
            for (int k = 0; k < 8; k++) {
                uint32_t kb = (uint32_t)k * 32;
                uint32_t a0, a1, a2, a3;
                LDMX4(a0, a1, a2, a3, ab + kb);
#pragma unroll
                for (int p = 0; p < 4; p++) {
                    uint32_t b0, b1, b2, b3;
                    LDMX4(b0, b1, b2, b3, bbs + boff[p] + kb);
                    MMA16816(acc[2 * p], a0, a1, a2, a3, b0, b1);
                    MMA16816(acc[2 * p + 1], a0, a1, a2, a3, b2, b3);
                }
            }
        }

        // ---- epilogue: d0,d1 = (row, col..col+1), d2,d3 = (row+8, ..) ----
        const int row_a = r0 + m0 + (lid >> 2);
        const int colb = 768 + c0 + (lid & 3) * 2;
#pragma unroll
        for (int nt = 0; nt < 8; nt++) {
            *(float2*)&out[(size_t)row_a * OUTW + colb + nt * 8] =
                make_float2(acc[nt][0], acc[nt][1]);
            *(float2*)&out[(size_t)(row_a + 8) * OUTW + colb + nt * 8] =
                make_float2(acc[nt][2], acc[nt][3]);
        }
    }

    // ---- basis: dense float2 stores, cardinal closed form ----
    {
        const float* xb = x + (size_t)r0 * D;
#pragma unroll 4
        for (int s = 0; s < BAS_ITERS; s++) {
            int q = tid + s * THREADS;          // 0..24575
            int row = q / SLOTS_PER_ROW;
            int p = q - row * SLOTS_PER_ROW;
            int i = p / 3;
            int pr = p - i * 3;

            float xv = __ldg(&xb[row * D + i]);
            float px = fminf(fmaxf(fmaf(xv, 4.5f, 4.5f), 0.0f), 8.9999955f);
            float y0 = px - (float)(2 * pr);
            float v0 = bspl(y0);
            float v1 = bspl(y0 - 1.0f);

            float2* op = (float2*)(out + (size_t)(r0 + row) * OUTW) + p;
            *op = make_float2(v0, v1);
        }
    }
}

extern "C" void kernel_launch(void* const* d_in, const int* in_sizes, int n_in,
                              void* d_out, int out_size) {
    const float* x;
    const float* W;
    if (n_in >= 2 && in_sizes[0] == D * D && in_sizes[1] != D * D) {
        W = (const float*)d_in[0];
        x = (const float*)d_in[1];
    } else {
        x = (const float*)d_in[0];
        W = (const float*)d_in[1];
    }
    float* out = (float*)d_out;

    cudaFuncSetAttribute(kan_kernel, cudaFuncAttributeMaxDynamicSharedMemorySize, SM_TOTAL);

    prep_kernel<<<(D * D + 255) / 256, 256>>>(W);
    kan_kernel<<<NBLOCKS, THREADS, SM_TOTAL>>>(x, out);
}